// round 3
// baseline (speedup 1.0000x reference)
#include <cuda_runtime.h>
#include <math.h>
#include <stdint.h>

#define HH   8
#define SS   1024
#define DDIM 64
#define KG   10
#define NLUT 4096
#define BM   64
#define BN   64
#define STR  72          // smem row stride (floats): 64 + 8 pad -> conflict-free fragments

#define D_LO (-0.05f)
#define D_HI (10.05f)
#define E_LO (-0.05f)
#define E_HI (5.05f)

__device__ float2 g_lutD[NLUT];
__device__ float2 g_lutE[NLUT];

// ---------------------------------------------------------------------------
// Exact bias function (RBF -> Linear -> exact GELU -> Linear), LUT build only.
// ---------------------------------------------------------------------------
__device__ __forceinline__ float bias_eval(
    float x,
    const float* __restrict__ mu, const float* __restrict__ sg,
    const float* __restrict__ bb,
    const float* __restrict__ W1, const float* __restrict__ b1,
    const float* __restrict__ W2, const float* __restrict__ b2)
{
    float psi[KG];
#pragma unroll
    for (int k = 0; k < KG; k++) {
        float s = sg[k];
        float z = (x + bb[k] - mu[k]) / s;
        psi[k] = expf(-0.5f * z * z) * (0.3989422804014327f / s);
    }
    float o = b2[0];
#pragma unroll
    for (int l = 0; l < KG; l++) {
        float a = b1[l];
#pragma unroll
        for (int k = 0; k < KG; k++) a = fmaf(psi[k], W1[l * KG + k], a);
        float g = 0.5f * a * (1.0f + erff(a * 0.7071067811865476f));
        o = fmaf(g, W2[l], o);
    }
    return o;
}

__global__ void build_lut_kernel(
    const float* __restrict__ muD, const float* __restrict__ sgD, const float* __restrict__ bD,
    const float* __restrict__ muE, const float* __restrict__ sgE, const float* __restrict__ bE,
    const float* __restrict__ W1,  const float* __restrict__ b1,
    const float* __restrict__ W2,  const float* __restrict__ b2)
{
    int i = blockIdx.x * blockDim.x + threadIdx.x;
    if (i >= 2 * NLUT) return;
    int which = i >> 12;
    int e     = i & (NLUT - 1);

    float lo = which ? E_LO : D_LO;
    float hi = which ? E_HI : D_HI;
    float dx = (hi - lo) / (float)(NLUT - 1);
    float x0 = lo + (float)e * dx;

    const float* mu = which ? muE : muD;
    const float* sg = which ? sgE : sgD;
    const float* bb = which ? bE  : bD;

    float f0 = bias_eval(x0,      mu, sg, bb, W1, b1, W2, b2);
    float f1 = bias_eval(x0 + dx, mu, sg, bb, W1, b1, W2, b2);
    float2 entry = make_float2(f0, f1 - f0);
    if (which) g_lutE[e] = entry; else g_lutD[e] = entry;
}

// ---------------------------------------------------------------------------
// tf32 helpers
// ---------------------------------------------------------------------------
__device__ __forceinline__ uint32_t f2tf(float x) {
    uint32_t r;
    asm("cvt.rna.tf32.f32 %0, %1;" : "=r"(r) : "f"(x));
    return r;
}

// x = hi + lo, both exactly representable in tf32 (lo captures the residual)
__device__ __forceinline__ void split_store(float* ph, float* pl, float x) {
    float hx = __uint_as_float(f2tf(x));
    *ph = hx;
    *pl = __uint_as_float(f2tf(x - hx));
}

// D += A(16x8) * B(8x8), tf32 inputs, fp32 accumulate
__device__ __forceinline__ void mma8(float c[4], const uint32_t a[4],
                                     uint32_t b0, uint32_t b1)
{
    asm volatile(
        "mma.sync.aligned.m16n8k8.row.col.f32.tf32.tf32.f32 "
        "{%0,%1,%2,%3}, {%4,%5,%6,%7}, {%8,%9}, {%0,%1,%2,%3};\n"
        : "+f"(c[0]), "+f"(c[1]), "+f"(c[2]), "+f"(c[3])
        : "r"(a[0]), "r"(a[1]), "r"(a[2]), "r"(a[3]), "r"(b0), "r"(b1));
}

__device__ __forceinline__ float bias_term(float x, float lo, float inv,
                                           const float2* __restrict__ lut)
{
    float t = fminf(fmaxf((x - lo) * inv, 0.0f), (float)(NLUT - 1) - 1e-3f);
    int   i = (int)t;
    float f = t - (float)i;
    float2 e = lut[i];
    return fmaf(f, e.y, e.x);
}

// ---------------------------------------------------------------------------
// Fused flash-attention, tensor-core (3xTF32) GEMMs + LUT biases.
// Grid (16, 8), 256 threads = 8 warps: warp w -> m16-block (w&3), n32-half (w>>2).
// Dynamic smem (~210KB): Qh,Ql,Kh,Kl,Vh,Vl,Ph,Pl tiles [64][72] + reductions + LUTs.
// ---------------------------------------------------------------------------
__global__ __launch_bounds__(256, 1) void attn_kernel(
    const float* __restrict__ Q,
    const float* __restrict__ Kg,
    const float* __restrict__ Vg,
    const float* __restrict__ dist,
    const float* __restrict__ energy,
    const int*   __restrict__ mask,
    float*       __restrict__ out)
{
    extern __shared__ float sm[];
    float* sQh = sm;
    float* sQl = sm + 1 * 64 * STR;
    float* sKh = sm + 2 * 64 * STR;
    float* sKl = sm + 3 * 64 * STR;
    float* sVh = sm + 4 * 64 * STR;
    float* sVl = sm + 5 * 64 * STR;
    float* sPh = sm + 6 * 64 * STR;
    float* sPl = sm + 7 * 64 * STR;
    float* redmax = sm + 8 * 64 * STR;       // [8 warps][16 rows]
    float* redsum = redmax + 128;            // [8 warps][16 rows]
    float* m_s    = redsum + 128;            // [64] running row max
    float* l_s    = m_s + 64;                // [64] running row sum
    float2* sLD   = (float2*)(l_s + 64);
    float2* sLE   = sLD + NLUT;

    const int tid   = threadIdx.x;
    const int w     = tid >> 5;
    const int lane  = tid & 31;
    const int g     = lane >> 2;     // mma group id
    const int m     = lane & 3;      // thread-in-group
    const int mblk  = w & 3;
    const int nhalf = w >> 2;
    const int h     = blockIdx.y;
    const int i0    = blockIdx.x * BM;

    const int lr0 = mblk * 16 + g;   // local row of fragment elems 0/1
    const int lr1 = lr0 + 8;         // local row of fragment elems 2/3
    const int r0g = i0 + lr0;        // global row

    const float SCALE = 0.08838834764831845f;   // 1/sqrt(2*D)
    const float DINVc = (float)(NLUT - 1) / (D_HI - D_LO);
    const float EINVc = (float)(NLUT - 1) / (E_HI - E_LO);

    // ---- one-time block init: LUTs, row stats, Q tile (tf32-split) ----
    for (int i = tid; i < NLUT; i += 256) { sLD[i] = g_lutD[i]; sLE[i] = g_lutE[i]; }
    if (tid < 64) { m_s[tid] = -1e30f; l_s[tid] = 0.0f; }

#pragma unroll
    for (int it = 0; it < 4; it++) {
        int lin = tid + it * 256;
        int row = lin >> 4, c4 = (lin & 15) * 4;
        float4 qv = *(const float4*)&Q[((size_t)h * SS + i0 + row) * DDIM + c4];
        float* qh = &sQh[row * STR + c4];
        float* ql = &sQl[row * STR + c4];
        split_store(qh + 0, ql + 0, qv.x);
        split_store(qh + 1, ql + 1, qv.y);
        split_store(qh + 2, ql + 2, qv.z);
        split_store(qh + 3, ql + 3, qv.w);
    }

    float oacc[4][4] = {};

    for (int jt = 0; jt < SS / BN; jt++) {
        const int j0 = jt * BN;
        __syncthreads();   // (A) previous tile fully consumed; stats updated

        // ---- K,V tiles -> smem with tf32 split ----
#pragma unroll
        for (int it = 0; it < 4; it++) {
            int lin = tid + it * 256;
            int row = lin >> 4, c4 = (lin & 15) * 4;
            size_t goff = ((size_t)h * SS + j0 + row) * DDIM + c4;
            float4 kv = *(const float4*)&Kg[goff];
            float4 vv = *(const float4*)&Vg[goff];
            float* kh = &sKh[row * STR + c4];  float* kl = &sKl[row * STR + c4];
            float* vh = &sVh[row * STR + c4];  float* vl = &sVl[row * STR + c4];
            split_store(kh + 0, kl + 0, kv.x);  split_store(kh + 1, kl + 1, kv.y);
            split_store(kh + 2, kl + 2, kv.z);  split_store(kh + 3, kl + 3, kv.w);
            split_store(vh + 0, vl + 0, vv.x);  split_store(vh + 1, vl + 1, vv.y);
            split_store(vh + 2, vl + 2, vv.z);  split_store(vh + 3, vl + 3, vv.w);
        }

        // ---- prefetch bias streams for this thread's 16 S elements ----
        const int jb = j0 + nhalf * 32;
        float2 fD[4][2], fE[4][2];
        int2   fM[4][2];
        {
            size_t ro0 = ((size_t)h * SS + r0g) * SS;
            size_t ro1 = ro0 + (size_t)8 * SS;
#pragma unroll
            for (int nt = 0; nt < 4; nt++) {
                int cc = jb + nt * 8 + 2 * m;
                fD[nt][0] = *(const float2*)&dist[ro0 + cc];
                fD[nt][1] = *(const float2*)&dist[ro1 + cc];
                fE[nt][0] = *(const float2*)&energy[ro0 + cc];
                fE[nt][1] = *(const float2*)&energy[ro1 + cc];
                fM[nt][0] = *(const int2*)&mask[ro0 + cc];
                fM[nt][1] = *(const int2*)&mask[ro1 + cc];
            }
        }
        __syncthreads();   // (B) tiles ready

        // ---- S = Q K^T via 3xTF32 mma ----
        float sacc[4][4] = {};
#pragma unroll
        for (int ks = 0; ks < 8; ks++) {
            const int ko = ks * 8 + m;
            uint32_t ah[4], al[4];
            ah[0] = __float_as_uint(sQh[lr0 * STR + ko]);
            ah[1] = __float_as_uint(sQh[lr1 * STR + ko]);
            ah[2] = __float_as_uint(sQh[lr0 * STR + ko + 4]);
            ah[3] = __float_as_uint(sQh[lr1 * STR + ko + 4]);
            al[0] = __float_as_uint(sQl[lr0 * STR + ko]);
            al[1] = __float_as_uint(sQl[lr1 * STR + ko]);
            al[2] = __float_as_uint(sQl[lr0 * STR + ko + 4]);
            al[3] = __float_as_uint(sQl[lr1 * STR + ko + 4]);
#pragma unroll
            for (int nt = 0; nt < 4; nt++) {
                int jl = nhalf * 32 + nt * 8 + g;
                uint32_t bh0 = __float_as_uint(sKh[jl * STR + ko]);
                uint32_t bh1 = __float_as_uint(sKh[jl * STR + ko + 4]);
                uint32_t bl0 = __float_as_uint(sKl[jl * STR + ko]);
                uint32_t bl1 = __float_as_uint(sKl[jl * STR + ko + 4]);
                mma8(sacc[nt], ah, bh0, bh1);
                mma8(sacc[nt], al, bh0, bh1);
                mma8(sacc[nt], ah, bl0, bl1);
            }
        }

        // ---- scale + LUT biases + mask (in accumulator layout) ----
#pragma unroll
        for (int nt = 0; nt < 4; nt++) {
            float v;
            v = sacc[nt][0] * SCALE + bias_term(fD[nt][0].x, D_LO, DINVc, sLD)
                                    + bias_term(fE[nt][0].x, E_LO, EINVc, sLE);
            sacc[nt][0] = fM[nt][0].x ? v : -1e9f;
            v = sacc[nt][1] * SCALE + bias_term(fD[nt][0].y, D_LO, DINVc, sLD)
                                    + bias_term(fE[nt][0].y, E_LO, EINVc, sLE);
            sacc[nt][1] = fM[nt][0].y ? v : -1e9f;
            v = sacc[nt][2] * SCALE + bias_term(fD[nt][1].x, D_LO, DINVc, sLD)
                                    + bias_term(fE[nt][1].x, E_LO, EINVc, sLE);
            sacc[nt][2] = fM[nt][1].x ? v : -1e9f;
            v = sacc[nt][3] * SCALE + bias_term(fD[nt][1].y, D_LO, DINVc, sLD)
                                    + bias_term(fE[nt][1].y, E_LO, EINVc, sLE);
            sacc[nt][3] = fM[nt][1].y ? v : -1e9f;
        }

        // ---- per-warp row maxima ----
        float mx0 = fmaxf(fmaxf(sacc[0][0], sacc[0][1]), fmaxf(sacc[1][0], sacc[1][1]));
        float mx1 = fmaxf(fmaxf(sacc[0][2], sacc[0][3]), fmaxf(sacc[1][2], sacc[1][3]));
        mx0 = fmaxf(mx0, fmaxf(fmaxf(sacc[2][0], sacc[2][1]), fmaxf(sacc[3][0], sacc[3][1])));
        mx1 = fmaxf(mx1, fmaxf(fmaxf(sacc[2][2], sacc[2][3]), fmaxf(sacc[3][2], sacc[3][3])));
#pragma unroll
        for (int o = 1; o < 4; o <<= 1) {
            mx0 = fmaxf(mx0, __shfl_xor_sync(0xffffffffu, mx0, o));
            mx1 = fmaxf(mx1, __shfl_xor_sync(0xffffffffu, mx1, o));
        }
        if (m == 0) { redmax[w * 16 + g] = mx0; redmax[w * 16 + 8 + g] = mx1; }
        __syncthreads();   // (C) redmax ready

        // ---- combine halves, exp, P store (split), row sums ----
        const int wp = w ^ 4;
        float mo0 = m_s[lr0], mo1 = m_s[lr1];
        float mn0 = fmaxf(mo0, fmaxf(redmax[w * 16 + g],     redmax[wp * 16 + g]));
        float mn1 = fmaxf(mo1, fmaxf(redmax[w * 16 + 8 + g], redmax[wp * 16 + 8 + g]));
        float al0 = __expf(mo0 - mn0), al1 = __expf(mo1 - mn1);

        float sum0 = 0.0f, sum1 = 0.0f;
#pragma unroll
        for (int nt = 0; nt < 4; nt++) {
            float p0 = __expf(sacc[nt][0] - mn0);
            float p1 = __expf(sacc[nt][1] - mn0);
            float p2 = __expf(sacc[nt][2] - mn1);
            float p3 = __expf(sacc[nt][3] - mn1);
            sum0 += p0 + p1;  sum1 += p2 + p3;

            int jl = nhalf * 32 + nt * 8 + 2 * m;
            float h0 = __uint_as_float(f2tf(p0)), h1 = __uint_as_float(f2tf(p1));
            float h2 = __uint_as_float(f2tf(p2)), h3 = __uint_as_float(f2tf(p3));
            *(float2*)&sPh[lr0 * STR + jl] = make_float2(h0, h1);
            *(float2*)&sPh[lr1 * STR + jl] = make_float2(h2, h3);
            *(float2*)&sPl[lr0 * STR + jl] =
                make_float2(__uint_as_float(f2tf(p0 - h0)), __uint_as_float(f2tf(p1 - h1)));
            *(float2*)&sPl[lr1 * STR + jl] =
                make_float2(__uint_as_float(f2tf(p2 - h2)), __uint_as_float(f2tf(p3 - h3)));
        }
#pragma unroll
        for (int o = 1; o < 4; o <<= 1) {
            sum0 += __shfl_xor_sync(0xffffffffu, sum0, o);
            sum1 += __shfl_xor_sync(0xffffffffu, sum1, o);
        }
        if (m == 0) { redsum[w * 16 + g] = sum0; redsum[w * 16 + 8 + g] = sum1; }
        __syncthreads();   // (D) redsum + P ready

        // ---- update running stats (one owner set per row) ----
        if (nhalf == 0 && m == 0) {
            l_s[lr0] = l_s[lr0] * al0 + redsum[w * 16 + g] + redsum[(w + 4) * 16 + g];
            l_s[lr1] = l_s[lr1] * al1 + redsum[w * 16 + 8 + g] + redsum[(w + 4) * 16 + 8 + g];
            m_s[lr0] = mn0;
            m_s[lr1] = mn1;
        }

        // ---- rescale O, then O += P V via 3xTF32 mma ----
#pragma unroll
        for (int nt = 0; nt < 4; nt++) {
            oacc[nt][0] *= al0;  oacc[nt][1] *= al0;
            oacc[nt][2] *= al1;  oacc[nt][3] *= al1;
        }
#pragma unroll
        for (int ks = 0; ks < 8; ks++) {
            const int ko = ks * 8 + m;
            uint32_t ah[4], al_[4];
            ah[0]  = __float_as_uint(sPh[lr0 * STR + ko]);
            ah[1]  = __float_as_uint(sPh[lr1 * STR + ko]);
            ah[2]  = __float_as_uint(sPh[lr0 * STR + ko + 4]);
            ah[3]  = __float_as_uint(sPh[lr1 * STR + ko + 4]);
            al_[0] = __float_as_uint(sPl[lr0 * STR + ko]);
            al_[1] = __float_as_uint(sPl[lr1 * STR + ko]);
            al_[2] = __float_as_uint(sPl[lr0 * STR + ko + 4]);
            al_[3] = __float_as_uint(sPl[lr1 * STR + ko + 4]);
#pragma unroll
            for (int nt = 0; nt < 4; nt++) {
                int dl = nhalf * 32 + nt * 8 + g;
                uint32_t bh0 = __float_as_uint(sVh[ko * STR + dl]);
                uint32_t bh1 = __float_as_uint(sVh[(ko + 4) * STR + dl]);
                uint32_t bl0 = __float_as_uint(sVl[ko * STR + dl]);
                uint32_t bl1 = __float_as_uint(sVl[(ko + 4) * STR + dl]);
                mma8(oacc[nt], ah,  bh0, bh1);
                mma8(oacc[nt], al_, bh0, bh1);
                mma8(oacc[nt], ah,  bl0, bl1);
            }
        }
    }

    // ---- normalize + write output ----
    __syncthreads();
    float inv0 = 1.0f / l_s[lr0];
    float inv1 = 1.0f / l_s[lr1];
#pragma unroll
    for (int nt = 0; nt < 4; nt++) {
        int dl = nhalf * 32 + nt * 8 + 2 * m;
        size_t o0 = ((size_t)h * SS + r0g) * DDIM + dl;
        *(float2*)&out[o0]            = make_float2(oacc[nt][0] * inv0, oacc[nt][1] * inv0);
        *(float2*)&out[o0 + 8 * DDIM] = make_float2(oacc[nt][2] * inv1, oacc[nt][3] * inv1);
    }
}

// ---------------------------------------------------------------------------
extern "C" void kernel_launch(void* const* d_in, const int* in_sizes, int n_in,
                              void* d_out, int out_size)
{
    const float* Q      = (const float*)d_in[0];
    const float* K      = (const float*)d_in[1];
    const float* V      = (const float*)d_in[2];
    const float* dist   = (const float*)d_in[3];
    const float* energy = (const float*)d_in[4];
    const int*   mask   = (const int*)  d_in[5];
    const float* mu_D   = (const float*)d_in[6];
    const float* sg_D   = (const float*)d_in[7];
    const float* b_D    = (const float*)d_in[8];
    const float* mu_E   = (const float*)d_in[9];
    const float* sg_E   = (const float*)d_in[10];
    const float* b_E    = (const float*)d_in[11];
    const float* W1     = (const float*)d_in[12];
    const float* b1     = (const float*)d_in[13];
    const float* W2     = (const float*)d_in[14];
    const float* b2     = (const float*)d_in[15];
    float* out = (float*)d_out;

    // 1) build the two bias LUTs
    build_lut_kernel<<<(2 * NLUT + 255) / 256, 256>>>(
        mu_D, sg_D, b_D, mu_E, sg_E, b_E, W1, b1, W2, b2);

    // 2) fused attention (tensor-core path)
    const int SMEM_BYTES = (8 * 64 * STR + 128 + 128 + 64 + 64) * 4 + 2 * NLUT * 8;
    cudaFuncSetAttribute(attn_kernel,
                         cudaFuncAttributeMaxDynamicSharedMemorySize, SMEM_BYTES);
    attn_kernel<<<dim3(SS / BM, HH), 256, SMEM_BYTES>>>(
        Q, K, V, dist, energy, mask, out);
}